// round 1
// baseline (speedup 1.0000x reference)
#include <cuda_runtime.h>
#include <cstdint>
#include <math.h>

typedef unsigned long long ull;

#define NN 512
#define DD 64
#define BB 8
#define KSEL 256
#define XP 258   // padded pitch for transposed x tile (floats)

// Scratch (static __device__ arrays: no allocation allowed)
__device__ float g_L[(size_t)BB * NN * NN];   // logits  8 MB
__device__ float g_h[(size_t)BB * NN * DD];   // h after selu
__device__ float g_s[(size_t)BB * NN];        // sigmoid scores

// ---------------------------------------------------------------------------
// Kernel 1: logits[b][i][j] = sum_o v[o]*tanh( sum_d x[b,i,d]*W[d,o]*x[b,j,d] + b[o] )
// Symmetric: CTA (b,i) computes k=(j-i) mod 512 in [0,255] (+256 if i<256),
// writes both [i][j] and [j][i]. Inner GEMM uses packed fma.rn.f32x2.
// ---------------------------------------------------------------------------
__global__ __launch_bounds__(256) void k1_logits(
    const float* __restrict__ x, const float* __restrict__ attw,
    const float* __restrict__ attb, const float* __restrict__ attv)
{
    extern __shared__ float smem[];
    float* xT  = smem;                         // [64][XP], jloc 0..256 used
    ull*   Wp2 = (ull*)(smem + 64 * XP);       // [64][64] lane-duplicated W'
    float* red = (float*)(Wp2 + 64 * 64);      // [8][256]
    float* vv  = red + 8 * 256;                // [64]
    float* bbv = vv + 64;                      // [64]

    const int i = blockIdx.x, b = blockIdx.y;
    const int tid = threadIdx.x;
    const int jg = tid & 31, og = tid >> 5;

    // Load x window (rows i..i+256 mod 512) transposed into smem
    for (int idx = tid; idx < 257 * 64; idx += 256) {
        int r = idx >> 6, d = idx & 63;
        int g = (i + r) & (NN - 1);
        xT[d * XP + r] = x[((size_t)b * NN + g) * DD + d];
    }
    if (tid < 64) { vv[tid] = attv[tid]; bbv[tid] = attb[tid]; }
    __syncthreads();

    // W'[d][o] = x[b,i,d] * W[d,o], duplicated into both f32x2 lanes
    for (int idx = tid; idx < 64 * 64; idx += 256) {
        int d = idx >> 6;
        float w = xT[d * XP] * attw[idx];
        ull wd; asm("mov.b64 %0,{%1,%1};" : "=l"(wd) : "f"(w));
        Wp2[idx] = wd;
    }
    __syncthreads();

    // Register tile: 8 j (4 pairs) x 8 o per thread; 256 threads cover 256 j x 64 o
    ull acc[4][8];
    #pragma unroll
    for (int r = 0; r < 4; r++)
        #pragma unroll
        for (int c = 0; c < 8; c++) acc[r][c] = 0ull;

    #pragma unroll 4
    for (int d = 0; d < 64; d++) {
        ull xp[4];
        #pragma unroll
        for (int r = 0; r < 4; r++)
            xp[r] = *(const ull*)&xT[d * XP + 2 * jg + 64 * r];
        ull wv[8];
        #pragma unroll
        for (int c = 0; c < 8; c++)
            wv[c] = Wp2[d * 64 + og * 8 + c];
        #pragma unroll
        for (int r = 0; r < 4; r++)
            #pragma unroll
            for (int c = 0; c < 8; c++)
                asm("fma.rn.f32x2 %0, %1, %2, %0;"
                    : "+l"(acc[r][c]) : "l"(xp[r]), "l"(wv[c]));
    }

    // Epilogue: tanh + reduce over o (v-weighted), partial per og group
    #pragma unroll
    for (int r = 0; r < 4; r++) {
        float plo = 0.f, phi = 0.f;
        #pragma unroll
        for (int c = 0; c < 8; c++) {
            int o = og * 8 + c;
            float lo, hi;
            asm("mov.b64 {%0,%1}, %2;" : "=f"(lo), "=f"(hi) : "l"(acc[r][c]));
            plo += vv[o] * tanhf(lo + bbv[o]);
            phi += vv[o] * tanhf(hi + bbv[o]);
        }
        int jloc = 2 * jg + 64 * r;
        red[og * 256 + jloc]     = plo;
        red[og * 256 + jloc + 1] = phi;
    }
    __syncthreads();
    {
        float s = 0.f;
        #pragma unroll
        for (int g = 0; g < 8; g++) s += red[g * 256 + tid];
        int jglob = (i + tid) & (NN - 1);
        g_L[((size_t)b * NN + i) * NN + jglob] = s;
        g_L[((size_t)b * NN + jglob) * NN + i] = s;   // symmetric mirror
    }

    // Tail k=256: single writer (i<256) for determinism
    if (i < 256) {
        __syncthreads();
        if (tid < 64) {
            float q = bbv[tid];
            #pragma unroll 8
            for (int d = 0; d < 64; d++)
                q += (xT[d * XP] * attw[d * 64 + tid]) * xT[d * XP + 256];
            red[tid] = vv[tid] * tanhf(q);
        }
        __syncthreads();
        if (tid == 0) {
            float s = 0.f;
            for (int o = 0; o < 64; o++) s += red[o];
            int jglob = (i + 256) & (NN - 1);
            g_L[((size_t)b * NN + i) * NN + jglob] = s;
            g_L[((size_t)b * NN + jglob) * NN + i] = s;
        }
    }
}

// ---------------------------------------------------------------------------
// Kernel 2: per (b,i): softmax over j, agg = att@x, h = agg@pwa + x@pwo + b,
// BN(eval) + selu, score = sigmoid(h@pool_w + pool_b)
// ---------------------------------------------------------------------------
__global__ __launch_bounds__(128) void k2_head(
    const float* __restrict__ x,
    const float* __restrict__ pwa_w, const float* __restrict__ pwa_b,
    const float* __restrict__ pwo_w, const float* __restrict__ pwo_b,
    const float* __restrict__ gamma, const float* __restrict__ beta,
    const float* __restrict__ poolw, const float* __restrict__ poolb)
{
    __shared__ float att[NN];
    __shared__ float xi[DD];
    __shared__ float agg[DD];
    __shared__ float aggp[128];
    __shared__ float sred[32];

    const int i = blockIdx.x, b = blockIdx.y, tid = threadIdx.x;
    const float* Lrow = &g_L[((size_t)b * NN + i) * NN];

    float lv[4], m = -1e30f;
    #pragma unroll
    for (int t = 0; t < 4; t++) { lv[t] = Lrow[tid + 128 * t]; m = fmaxf(m, lv[t]); }
    #pragma unroll
    for (int off = 16; off; off >>= 1) m = fmaxf(m, __shfl_xor_sync(~0u, m, off));
    if ((tid & 31) == 0) sred[tid >> 5] = m;
    __syncthreads();
    if (tid == 0) sred[8] = fmaxf(fmaxf(sred[0], sred[1]), fmaxf(sred[2], sred[3]));
    __syncthreads();
    const float M = sred[8];

    float s = 0.f;
    #pragma unroll
    for (int t = 0; t < 4; t++) {
        float e = expf(lv[t] - M);
        att[tid + 128 * t] = e;
        s += e;
    }
    #pragma unroll
    for (int off = 16; off; off >>= 1) s += __shfl_xor_sync(~0u, s, off);
    if ((tid & 31) == 0) sred[16 + (tid >> 5)] = s;
    if (tid < DD) xi[tid] = x[((size_t)b * NN + i) * DD + tid];
    __syncthreads();
    const float inv = 1.0f / (sred[16] + sred[17] + sred[18] + sred[19]);
    #pragma unroll
    for (int t = 0; t < 4; t++) att[tid + 128 * t] *= inv;
    __syncthreads();

    // agg[d] = sum_j att[j] * x[b,j,d] (split over 2 j-halves)
    const int d = tid & 63, half = tid >> 6;
    const float* xb = &x[(size_t)b * NN * DD];
    float a = 0.f;
    #pragma unroll 8
    for (int j = half * 256; j < half * 256 + 256; j++)
        a += att[j] * xb[(size_t)j * DD + d];
    aggp[tid] = a;
    __syncthreads();
    if (tid < DD) agg[tid] = aggp[tid] + aggp[tid + 64];
    __syncthreads();

    if (tid < DD) {
        const int o = tid;
        float hv = pwa_b[o] + pwo_b[o];
        #pragma unroll 8
        for (int dd = 0; dd < 64; dd++)
            hv += agg[dd] * pwa_w[dd * 64 + o] + xi[dd] * pwo_w[dd * 64 + o];
        hv = hv / sqrtf(1.0f + 1e-5f) * gamma[o] + beta[o];
        const float SC = 1.0507009873554804934193349852946f;
        const float AL = 1.6732632423543772848170429916717f;
        hv = hv > 0.f ? SC * hv : SC * AL * expm1f(hv);
        g_h[((size_t)b * NN + i) * DD + o] = hv;
        float p = hv * poolw[o];
        #pragma unroll
        for (int off = 16; off; off >>= 1) p += __shfl_xor_sync(~0u, p, off);
        if ((tid & 31) == 0) sred[24 + (tid >> 5)] = p;
    }
    __syncthreads();
    if (tid == 0) {
        float z = sred[24] + sred[25] + poolb[0];
        g_s[(size_t)b * NN + i] = 1.0f / (1.0f + expf(-z));
    }
}

// ---------------------------------------------------------------------------
// Kernel 3: per batch, descending top-256 (stable: lower idx wins ties),
// gather out[b][r] = h[b][idx_r] * score[idx_r]
// ---------------------------------------------------------------------------
__global__ __launch_bounds__(512) void k3_topk(float* __restrict__ out)
{
    __shared__ ull keys[NN];
    const int b = blockIdx.x, tid = threadIdx.x;
    {
        float sc = g_s[(size_t)b * NN + tid];
        // sort key: score (positive float bits, order-preserving) | (511-idx) for
        // stable lower-index-first on ties when read in descending order
        keys[tid] = ((ull)__float_as_uint(sc) << 32) | (ull)(unsigned)(511 - tid);
    }
    __syncthreads();
    // bitonic sort ascending
    for (int k = 2; k <= NN; k <<= 1) {
        for (int j = k >> 1; j > 0; j >>= 1) {
            int ixj = tid ^ j;
            if (ixj > tid) {
                ull a = keys[tid], c = keys[ixj];
                bool asc = (tid & k) == 0;
                if ((a > c) == asc) { keys[tid] = c; keys[ixj] = a; }
            }
            __syncthreads();
        }
    }
    // rank r (descending) = keys[511 - r]; 2 threads per output row
    const int r = tid >> 1, ho = (tid & 1) * 32;
    ull key = keys[(NN - 1) - r];
    float sc = __uint_as_float((unsigned)(key >> 32));
    int idx = 511 - (int)(key & 0xffffffffu);
    const float* hr = &g_h[((size_t)b * NN + idx) * DD];
    float* orow = &out[((size_t)b * KSEL + r) * DD];
    #pragma unroll
    for (int c = 0; c < 32; c++)
        orow[ho + c] = hr[ho + c] * sc;
}

// ---------------------------------------------------------------------------
extern "C" void kernel_launch(void* const* d_in, const int* in_sizes, int n_in,
                              void* d_out, int out_size)
{
    (void)in_sizes; (void)n_in; (void)out_size;
    const float* x      = (const float*)d_in[0];
    const float* attw   = (const float*)d_in[1];
    const float* attb   = (const float*)d_in[2];
    const float* attv   = (const float*)d_in[3];
    const float* pwa_w  = (const float*)d_in[4];
    const float* pwa_b  = (const float*)d_in[5];
    const float* pwo_w  = (const float*)d_in[6];
    const float* pwo_b  = (const float*)d_in[7];
    const float* gamma  = (const float*)d_in[8];
    const float* beta   = (const float*)d_in[9];
    const float* poolw  = (const float*)d_in[10];
    const float* poolb  = (const float*)d_in[11];

    const int SMEM1 = (64 * XP + 2 * 64 * 64 + 8 * 256 + 128) * (int)sizeof(float);
    cudaFuncSetAttribute(k1_logits, cudaFuncAttributeMaxDynamicSharedMemorySize, SMEM1);

    dim3 g1(NN, BB);
    k1_logits<<<g1, 256, SMEM1>>>(x, attw, attb, attv);
    dim3 g2(NN, BB);
    k2_head<<<g2, 128>>>(x, pwa_w, pwa_b, pwo_w, pwo_b, gamma, beta, poolw, poolb);
    k3_topk<<<BB, NN>>>((float*)d_out);
}